// round 9
// baseline (speedup 1.0000x reference)
#include <cuda_runtime.h>
#include <cuda_fp16.h>
#include <cstdint>

#define NN 100000
#define DF 64
#define NE 1600000
#define NB ((NN + 1023) / 1024)   // 98 scan blocks

static constexpr float DTC     = 0.2f;
static constexpr float HALF_DT = 0.1f;
static constexpr float DT6     = 0.2f / 6.0f;

// ---------------- scratch (static device globals) ----------------
__device__ int     g_deg1[NN];          // masked row degree (hop-1 CSR)
__device__ int     g_deg2[NN];          // full row degree   (hop-2 CSR)
__device__ int     g_deg_c[NN];         // full col degree
__device__ int     g_cur1[NN];
__device__ int     g_cur2[NN];
__device__ float   g_dinv_r[NN];        // row factor (applied to warp sum)
__device__ float   g_premul[NN];        // mask * dinv_c (folded into u)
__device__ float   g_dd[NN];            // dinv_r * dinv_c (folded into t1)
__device__ int     g_rp1[NN + 1];
__device__ int     g_rp2[NN + 1];
__device__ int     g_part1[NB];
__device__ int     g_part2[NB];
__device__ int     g_ecol1[NE];         // masked CSR cols (~half used)
__device__ int     g_ecol2[NE];         // full CSR cols
__device__ __half2 g_uh [NN * DF / 2];  // stage input * mask*dinv_c, fp16
__device__ __half2 g_t1h[NN * DF / 2];  // hop-1 out * dinv_r*dinv_c, fp16
__device__ __half2 g_rh [NN * DF / 2];  // fp16 copy of current state r
__device__ float2  g_acc[NN * DF / 2];  // k1 + 2k2 + 2k3

// ---------------- preprocessing ----------------
__global__ void zero_kernel() {
    int i = blockIdx.x * blockDim.x + threadIdx.x;
    if (i < NN) { g_deg1[i] = 0; g_deg2[i] = 0; g_deg_c[i] = 0;
                  g_cur1[i] = 0; g_cur2[i] = 0; }
}

__global__ void hist_kernel(const int* __restrict__ row, const int* __restrict__ col,
                            const int* __restrict__ mask) {
    int e = blockIdx.x * blockDim.x + threadIdx.x;
    if (e < NE) {
        int r = row[e], c = col[e];
        atomicAdd(&g_deg2[r], 1);
        atomicAdd(&g_deg_c[c], 1);
        if (mask[c]) atomicAdd(&g_deg1[r], 1);
    }
}

__global__ void dinv_kernel(const int* __restrict__ mask) {
    int i = blockIdx.x * blockDim.x + threadIdx.x;
    if (i < NN) {
        int dr = g_deg2[i];
        int dc = g_deg_c[i];
        float ir = dr > 0 ? rsqrtf((float)dr) : 0.0f;
        float ic = dc > 0 ? rsqrtf((float)dc) : 0.0f;
        g_dinv_r[i] = ir;
        g_premul[i] = mask[i] ? ic : 0.0f;
        g_dd[i]     = ir * ic;
    }
}

// Fused two-level scans for BOTH CSRs (blocks [0,NB) -> CSR1, [NB,2NB) -> CSR2)
__global__ void scan_block_fused() {
    int bb = blockIdx.x;
    int isP2 = (bb >= NB);
    int b = isP2 ? bb - NB : bb;
    const int* __restrict__ deg = isP2 ? g_deg2  : g_deg1;
    int* __restrict__ rp        = isP2 ? g_rp2   : g_rp1;
    int* __restrict__ part      = isP2 ? g_part2 : g_part1;
    __shared__ int wsum[32];
    int t = threadIdx.x, lane = t & 31, wid = t >> 5;
    int i = b * 1024 + t;
    int v = (i < NN) ? deg[i] : 0;
    int incl = v;
    #pragma unroll
    for (int off = 1; off < 32; off <<= 1) {
        int x = __shfl_up_sync(0xffffffffu, incl, off);
        if (lane >= off) incl += x;
    }
    if (lane == 31) wsum[wid] = incl;
    __syncthreads();
    if (wid == 0) {
        int ws = wsum[lane];
        int wincl = ws;
        #pragma unroll
        for (int off = 1; off < 32; off <<= 1) {
            int x = __shfl_up_sync(0xffffffffu, wincl, off);
            if (lane >= off) wincl += x;
        }
        wsum[lane] = wincl - ws;
    }
    __syncthreads();
    int excl = incl - v + wsum[wid];
    if (i < NN) rp[i] = excl;
    if (t == 1023) part[b] = excl + v;
}

__global__ void scan_part_fused() {
    int t = threadIdx.x;
    if (t == 0) {
        int s = 0;
        for (int b = 0; b < NB; b++) { int v = g_part1[b]; g_part1[b] = s; s += v; }
        g_rp1[NN] = s;
    } else if (t == 32) {
        int s = 0;
        for (int b = 0; b < NB; b++) { int v = g_part2[b]; g_part2[b] = s; s += v; }
        g_rp2[NN] = s;
    }
}

__global__ void scan_add_fused() {
    int bb = blockIdx.x;
    int isP2 = (bb >= NB);
    int b = isP2 ? bb - NB : bb;
    int* __restrict__ rp   = isP2 ? g_rp2   : g_rp1;
    const int* __restrict__ part = isP2 ? g_part2 : g_part1;
    int i = b * 1024 + threadIdx.x;
    if (i < NN) rp[i] += part[b];
}

__global__ void scatter_kernel(const int* __restrict__ row, const int* __restrict__ col,
                               const int* __restrict__ mask) {
    int e = blockIdx.x * blockDim.x + threadIdx.x;
    if (e < NE) {
        int r = row[e], c = col[e];
        int p2 = g_rp2[r] + atomicAdd(&g_cur2[r], 1);
        g_ecol2[p2] = c;
        if (mask[c]) {
            int p1 = g_rp1[r] + atomicAdd(&g_cur1[r], 1);
            g_ecol1[p1] = c;
        }
    }
}

// uh = mask*dinv_c * r0; rh = fp16(r0)
__global__ void init_u_kernel(const float* __restrict__ r0) {
    int i = blockIdx.x * blockDim.x + threadIdx.x;   // float2 index
    if (i < NN * DF / 2) {
        int node = i >> 5;
        float p = g_premul[node];
        float2 r = ((const float2*)r0)[i];
        g_uh[i] = __floats2half2_rn(p * r.x, p * r.y);
        g_rh[i] = __floats2half2_rn(r.x, r.y);
    }
}

// ---------------- gather core: warp per row, cascaded 16/8/serial batches ----
// Per 32-edge chunk: one coalesced col load; consume with a 16-wide batch
// (16 shfl + 16 independent LDG.32 before accumulation), then an 8-wide batch,
// then a serial tail. Explicit scalars only (no local arrays -> no spill).
__device__ __forceinline__ float2
row_gather(const __half2* __restrict__ x, const int* __restrict__ ec,
           int s, int e, int lane) {
    float a0 = 0.0f, a1 = 0.0f;
    for (int base = s; base < e; base += 32) {
        int idx = base + lane;
        int c = (idx < e) ? __ldg(&ec[idx]) : 0;
        int n = min(32, e - base);
        int j = 0;
        for (; j + 16 <= n; j += 16) {
            int c0  = __shfl_sync(0xffffffffu, c, j + 0);
            int c1  = __shfl_sync(0xffffffffu, c, j + 1);
            int c2  = __shfl_sync(0xffffffffu, c, j + 2);
            int c3  = __shfl_sync(0xffffffffu, c, j + 3);
            int c4  = __shfl_sync(0xffffffffu, c, j + 4);
            int c5  = __shfl_sync(0xffffffffu, c, j + 5);
            int c6  = __shfl_sync(0xffffffffu, c, j + 6);
            int c7  = __shfl_sync(0xffffffffu, c, j + 7);
            int c8  = __shfl_sync(0xffffffffu, c, j + 8);
            int c9  = __shfl_sync(0xffffffffu, c, j + 9);
            int c10 = __shfl_sync(0xffffffffu, c, j + 10);
            int c11 = __shfl_sync(0xffffffffu, c, j + 11);
            int c12 = __shfl_sync(0xffffffffu, c, j + 12);
            int c13 = __shfl_sync(0xffffffffu, c, j + 13);
            int c14 = __shfl_sync(0xffffffffu, c, j + 14);
            int c15 = __shfl_sync(0xffffffffu, c, j + 15);
            __half2 v0  = __ldg(&x[c0  * (DF / 2) + lane]);
            __half2 v1  = __ldg(&x[c1  * (DF / 2) + lane]);
            __half2 v2  = __ldg(&x[c2  * (DF / 2) + lane]);
            __half2 v3  = __ldg(&x[c3  * (DF / 2) + lane]);
            __half2 v4  = __ldg(&x[c4  * (DF / 2) + lane]);
            __half2 v5  = __ldg(&x[c5  * (DF / 2) + lane]);
            __half2 v6  = __ldg(&x[c6  * (DF / 2) + lane]);
            __half2 v7  = __ldg(&x[c7  * (DF / 2) + lane]);
            __half2 v8  = __ldg(&x[c8  * (DF / 2) + lane]);
            __half2 v9  = __ldg(&x[c9  * (DF / 2) + lane]);
            __half2 v10 = __ldg(&x[c10 * (DF / 2) + lane]);
            __half2 v11 = __ldg(&x[c11 * (DF / 2) + lane]);
            __half2 v12 = __ldg(&x[c12 * (DF / 2) + lane]);
            __half2 v13 = __ldg(&x[c13 * (DF / 2) + lane]);
            __half2 v14 = __ldg(&x[c14 * (DF / 2) + lane]);
            __half2 v15 = __ldg(&x[c15 * (DF / 2) + lane]);
            float2 f;
            f = __half22float2(v0);  a0 += f.x; a1 += f.y;
            f = __half22float2(v1);  a0 += f.x; a1 += f.y;
            f = __half22float2(v2);  a0 += f.x; a1 += f.y;
            f = __half22float2(v3);  a0 += f.x; a1 += f.y;
            f = __half22float2(v4);  a0 += f.x; a1 += f.y;
            f = __half22float2(v5);  a0 += f.x; a1 += f.y;
            f = __half22float2(v6);  a0 += f.x; a1 += f.y;
            f = __half22float2(v7);  a0 += f.x; a1 += f.y;
            f = __half22float2(v8);  a0 += f.x; a1 += f.y;
            f = __half22float2(v9);  a0 += f.x; a1 += f.y;
            f = __half22float2(v10); a0 += f.x; a1 += f.y;
            f = __half22float2(v11); a0 += f.x; a1 += f.y;
            f = __half22float2(v12); a0 += f.x; a1 += f.y;
            f = __half22float2(v13); a0 += f.x; a1 += f.y;
            f = __half22float2(v14); a0 += f.x; a1 += f.y;
            f = __half22float2(v15); a0 += f.x; a1 += f.y;
        }
        if (j + 8 <= n) {
            int c0 = __shfl_sync(0xffffffffu, c, j + 0);
            int c1 = __shfl_sync(0xffffffffu, c, j + 1);
            int c2 = __shfl_sync(0xffffffffu, c, j + 2);
            int c3 = __shfl_sync(0xffffffffu, c, j + 3);
            int c4 = __shfl_sync(0xffffffffu, c, j + 4);
            int c5 = __shfl_sync(0xffffffffu, c, j + 5);
            int c6 = __shfl_sync(0xffffffffu, c, j + 6);
            int c7 = __shfl_sync(0xffffffffu, c, j + 7);
            __half2 v0 = __ldg(&x[c0 * (DF / 2) + lane]);
            __half2 v1 = __ldg(&x[c1 * (DF / 2) + lane]);
            __half2 v2 = __ldg(&x[c2 * (DF / 2) + lane]);
            __half2 v3 = __ldg(&x[c3 * (DF / 2) + lane]);
            __half2 v4 = __ldg(&x[c4 * (DF / 2) + lane]);
            __half2 v5 = __ldg(&x[c5 * (DF / 2) + lane]);
            __half2 v6 = __ldg(&x[c6 * (DF / 2) + lane]);
            __half2 v7 = __ldg(&x[c7 * (DF / 2) + lane]);
            float2 f;
            f = __half22float2(v0); a0 += f.x; a1 += f.y;
            f = __half22float2(v1); a0 += f.x; a1 += f.y;
            f = __half22float2(v2); a0 += f.x; a1 += f.y;
            f = __half22float2(v3); a0 += f.x; a1 += f.y;
            f = __half22float2(v4); a0 += f.x; a1 += f.y;
            f = __half22float2(v5); a0 += f.x; a1 += f.y;
            f = __half22float2(v6); a0 += f.x; a1 += f.y;
            f = __half22float2(v7); a0 += f.x; a1 += f.y;
            j += 8;
        }
        for (; j < n; j++) {
            int cj = __shfl_sync(0xffffffffu, c, j);
            float2 f = __half22float2(__ldg(&x[cj * (DF / 2) + lane]));
            a0 += f.x;
            a1 += f.y;
        }
    }
    return make_float2(a0, a1);
}

// hop-1: t1h[i] = dd[i] * sum_{masked e} uh[col_e]  (masked CSR)
__global__ void __launch_bounds__(256)
hop1_kernel() {
    int wi = (blockIdx.x * blockDim.x + threadIdx.x) >> 5;
    if (wi >= NN) return;
    int lane = threadIdx.x & 31;
    float2 sum = row_gather(g_uh, g_ecol1, g_rp1[wi], g_rp1[wi + 1], lane);
    float sc = g_dd[wi];
    g_t1h[wi * (DF / 2) + lane] = __floats2half2_rn(sc * sum.x, sc * sum.y);
}

// hop-2 + RK4 epilogue. v = -dinv_r[i] * sum_e t1h[col_e]  (full CSR)
// MODE 1 (k1): acc  = v;  u = rh + 0.5*dt*v        (rh = fp16 copy of r)
// MODE 2 (k2): acc += 2v; u = rh + 0.5*dt*v
// MODE 3 (k3): acc += 2v; u = rh +     dt*v
// MODE 4 (k4): rnext = r + dt/6*(acc + v) [fp32];  u = rnext; rh = rnext
template <int MODE>
__global__ void __launch_bounds__(256)
hop2_kernel(const float* __restrict__ rin, float* __restrict__ outparam) {
    int wi = (blockIdx.x * blockDim.x + threadIdx.x) >> 5;
    if (wi >= NN) return;
    int lane = threadIdx.x & 31;
    float2 sum = row_gather(g_t1h, g_ecol2, g_rp2[wi], g_rp2[wi + 1], lane);
    float sr = g_dinv_r[wi];
    float v0 = -sr * sum.x;
    float v1 = -sr * sum.y;

    int o = wi * (DF / 2) + lane;
    float p = g_premul[wi];

    if (MODE == 1) {
        g_acc[o] = make_float2(v0, v1);
        float2 rh = __half22float2(g_rh[o]);
        float u0 = rh.x + HALF_DT * v0, u1 = rh.y + HALF_DT * v1;
        g_uh[o] = __floats2half2_rn(p * u0, p * u1);
    } else if (MODE == 2) {
        float2 a = g_acc[o];
        g_acc[o] = make_float2(a.x + 2.0f * v0, a.y + 2.0f * v1);
        float2 rh = __half22float2(g_rh[o]);
        float u0 = rh.x + HALF_DT * v0, u1 = rh.y + HALF_DT * v1;
        g_uh[o] = __floats2half2_rn(p * u0, p * u1);
    } else if (MODE == 3) {
        float2 a = g_acc[o];
        g_acc[o] = make_float2(a.x + 2.0f * v0, a.y + 2.0f * v1);
        float2 rh = __half22float2(g_rh[o]);
        float u0 = rh.x + DTC * v0, u1 = rh.y + DTC * v1;
        g_uh[o] = __floats2half2_rn(p * u0, p * u1);
    } else {  // MODE 4
        float2 a = g_acc[o];
        float2 r2 = ((const float2*)rin)[o];
        float rn0 = r2.x + DT6 * (a.x + v0);
        float rn1 = r2.y + DT6 * (a.y + v1);
        ((float2*)outparam)[o] = make_float2(rn0, rn1);
        g_rh[o] = __floats2half2_rn(rn0, rn1);
        g_uh[o] = __floats2half2_rn(p * rn0, p * rn1);  // next step's k1 input
    }
}

// ---------------- launch ----------------
extern "C" void kernel_launch(void* const* d_in, const int* in_sizes, int n_in,
                              void* d_out, int out_size) {
    const float* r0   = (const float*)d_in[0];
    const int*   eidx = (const int*)d_in[1];
    const int*   mask = (const int*)d_in[2];
    const int* row = eidx;
    const int* col = eidx + NE;
    float* out = (float*)d_out;

    // CSR + normalization build (no device-global symbols passed from host!)
    zero_kernel<<<(NN + 255) / 256, 256>>>();
    hist_kernel<<<(NE + 255) / 256, 256>>>(row, col, mask);
    dinv_kernel<<<(NN + 255) / 256, 256>>>(mask);
    scan_block_fused<<<2 * NB, 1024>>>();
    scan_part_fused <<<1, 64>>>();
    scan_add_fused  <<<2 * NB, 1024>>>();
    scatter_kernel  <<<(NE + 255) / 256, 256>>>(row, col, mask);

    // slice 0 = r0; uh = premul * r0; rh = fp16(r0)
    cudaMemcpyAsync(out, r0, (size_t)NN * DF * sizeof(float),
                    cudaMemcpyDeviceToDevice, 0);
    init_u_kernel<<<(NN * DF / 2 + 255) / 256, 256>>>(r0);

    const int blocks = (NN * 32 + 255) / 256;  // warp per row

    for (int step = 0; step < 5; step++) {
        const float* r = out + (size_t)step * NN * DF;
        float* rnext   = out + (size_t)(step + 1) * NN * DF;

        hop1_kernel   <<<blocks, 256>>>();
        hop2_kernel<1><<<blocks, 256>>>(r, nullptr);
        hop1_kernel   <<<blocks, 256>>>();
        hop2_kernel<2><<<blocks, 256>>>(r, nullptr);
        hop1_kernel   <<<blocks, 256>>>();
        hop2_kernel<3><<<blocks, 256>>>(r, nullptr);
        hop1_kernel   <<<blocks, 256>>>();
        hop2_kernel<4><<<blocks, 256>>>(r, rnext);
    }
}

// round 10
// speedup vs baseline: 1.2308x; 1.2308x over previous
#include <cuda_runtime.h>
#include <cuda_fp16.h>
#include <cstdint>

#define NN 100000
#define DF 64
#define NE 1600000
#define NB ((NN + 1023) / 1024)   // 98 scan blocks

static constexpr float DTC     = 0.2f;
static constexpr float HALF_DT = 0.1f;
static constexpr float DT6     = 0.2f / 6.0f;

// ---------------- scratch (static device globals) ----------------
__device__ int     g_deg1[NN];          // masked row degree (hop-1 CSR)
__device__ int     g_deg2[NN];          // full row degree   (hop-2 CSR)
__device__ int     g_deg_c[NN];         // full col degree
__device__ int     g_cur1[NN];
__device__ int     g_cur2[NN];
__device__ float   g_dinv_r[NN];        // row factor (applied to warp sum)
__device__ float   g_premul[NN];        // mask * dinv_c (folded into u)
__device__ float   g_dd[NN];            // dinv_r * dinv_c (folded into t1)
__device__ int     g_rp1[NN + 1];
__device__ int     g_rp2[NN + 1];
__device__ int     g_part1[NB];
__device__ int     g_part2[NB];
__device__ int     g_ecol1[NE];         // masked CSR cols (~half used)
__device__ int     g_ecol2[NE];         // full CSR cols
__device__ __half2 g_uh [NN * DF / 2];  // stage input * mask*dinv_c, fp16
__device__ __half2 g_t1h[NN * DF / 2];  // hop-1 out * dinv_r*dinv_c, fp16
__device__ __half2 g_rh [NN * DF / 2];  // fp16 copy of current state r
__device__ float2  g_acc[NN * DF / 2];  // k1 + 2k2 + 2k3

// ---------------- preprocessing ----------------
__global__ void zero_kernel() {
    int i = blockIdx.x * blockDim.x + threadIdx.x;
    if (i < NN) { g_deg1[i] = 0; g_deg2[i] = 0; g_deg_c[i] = 0;
                  g_cur1[i] = 0; g_cur2[i] = 0; }
}

__global__ void hist_kernel(const int* __restrict__ row, const int* __restrict__ col,
                            const int* __restrict__ mask) {
    int e = blockIdx.x * blockDim.x + threadIdx.x;
    if (e < NE) {
        int r = row[e], c = col[e];
        atomicAdd(&g_deg2[r], 1);
        atomicAdd(&g_deg_c[c], 1);
        if (mask[c]) atomicAdd(&g_deg1[r], 1);
    }
}

__global__ void dinv_kernel(const int* __restrict__ mask) {
    int i = blockIdx.x * blockDim.x + threadIdx.x;
    if (i < NN) {
        int dr = g_deg2[i];
        int dc = g_deg_c[i];
        float ir = dr > 0 ? rsqrtf((float)dr) : 0.0f;
        float ic = dc > 0 ? rsqrtf((float)dc) : 0.0f;
        g_dinv_r[i] = ir;
        g_premul[i] = mask[i] ? ic : 0.0f;
        g_dd[i]     = ir * ic;
    }
}

// Fused two-level scans for BOTH CSRs (blocks [0,NB) -> CSR1, [NB,2NB) -> CSR2)
__global__ void scan_block_fused() {
    int bb = blockIdx.x;
    int isP2 = (bb >= NB);
    int b = isP2 ? bb - NB : bb;
    const int* __restrict__ deg = isP2 ? g_deg2  : g_deg1;
    int* __restrict__ rp        = isP2 ? g_rp2   : g_rp1;
    int* __restrict__ part      = isP2 ? g_part2 : g_part1;
    __shared__ int wsum[32];
    int t = threadIdx.x, lane = t & 31, wid = t >> 5;
    int i = b * 1024 + t;
    int v = (i < NN) ? deg[i] : 0;
    int incl = v;
    #pragma unroll
    for (int off = 1; off < 32; off <<= 1) {
        int x = __shfl_up_sync(0xffffffffu, incl, off);
        if (lane >= off) incl += x;
    }
    if (lane == 31) wsum[wid] = incl;
    __syncthreads();
    if (wid == 0) {
        int ws = wsum[lane];
        int wincl = ws;
        #pragma unroll
        for (int off = 1; off < 32; off <<= 1) {
            int x = __shfl_up_sync(0xffffffffu, wincl, off);
            if (lane >= off) wincl += x;
        }
        wsum[lane] = wincl - ws;
    }
    __syncthreads();
    int excl = incl - v + wsum[wid];
    if (i < NN) rp[i] = excl;
    if (t == 1023) part[b] = excl + v;
}

__global__ void scan_part_fused() {
    int t = threadIdx.x;
    if (t == 0) {
        int s = 0;
        for (int b = 0; b < NB; b++) { int v = g_part1[b]; g_part1[b] = s; s += v; }
        g_rp1[NN] = s;
    } else if (t == 32) {
        int s = 0;
        for (int b = 0; b < NB; b++) { int v = g_part2[b]; g_part2[b] = s; s += v; }
        g_rp2[NN] = s;
    }
}

__global__ void scan_add_fused() {
    int bb = blockIdx.x;
    int isP2 = (bb >= NB);
    int b = isP2 ? bb - NB : bb;
    int* __restrict__ rp         = isP2 ? g_rp2   : g_rp1;
    const int* __restrict__ part = isP2 ? g_part2 : g_part1;
    int i = b * 1024 + threadIdx.x;
    if (i < NN) rp[i] += part[b];
}

__global__ void scatter_kernel(const int* __restrict__ row, const int* __restrict__ col,
                               const int* __restrict__ mask) {
    int e = blockIdx.x * blockDim.x + threadIdx.x;
    if (e < NE) {
        int r = row[e], c = col[e];
        int p2 = g_rp2[r] + atomicAdd(&g_cur2[r], 1);
        g_ecol2[p2] = c;
        if (mask[c]) {
            int p1 = g_rp1[r] + atomicAdd(&g_cur1[r], 1);
            g_ecol1[p1] = c;
        }
    }
}

// uh = mask*dinv_c * r0; rh = fp16(r0)
__global__ void init_u_kernel(const float* __restrict__ r0) {
    int i = blockIdx.x * blockDim.x + threadIdx.x;   // float2 index
    if (i < NN * DF / 2) {
        int node = i >> 5;
        float p = g_premul[node];
        float2 r = ((const float2*)r0)[i];
        g_uh[i] = __floats2half2_rn(p * r.x, p * r.y);
        g_rh[i] = __floats2half2_rn(r.x, r.y);
    }
}

// ---------------- gather core: warp per row, group-of-8 batched loads ----------
// (R8-proven: batch = 8 keeps regs ~40 -> full occupancy; 16 was a regression)
__device__ __forceinline__ float2
row_gather(const __half2* __restrict__ x, const int* __restrict__ ec,
           int s, int e, int lane) {
    float a0 = 0.0f, a1 = 0.0f;
    for (int base = s; base < e; base += 32) {
        int idx = base + lane;
        int c = (idx < e) ? __ldg(&ec[idx]) : 0;
        int n = min(32, e - base);
        int j = 0;
        for (; j + 8 <= n; j += 8) {
            int c0 = __shfl_sync(0xffffffffu, c, j + 0);
            int c1 = __shfl_sync(0xffffffffu, c, j + 1);
            int c2 = __shfl_sync(0xffffffffu, c, j + 2);
            int c3 = __shfl_sync(0xffffffffu, c, j + 3);
            int c4 = __shfl_sync(0xffffffffu, c, j + 4);
            int c5 = __shfl_sync(0xffffffffu, c, j + 5);
            int c6 = __shfl_sync(0xffffffffu, c, j + 6);
            int c7 = __shfl_sync(0xffffffffu, c, j + 7);
            __half2 v0 = __ldg(&x[c0 * (DF / 2) + lane]);
            __half2 v1 = __ldg(&x[c1 * (DF / 2) + lane]);
            __half2 v2 = __ldg(&x[c2 * (DF / 2) + lane]);
            __half2 v3 = __ldg(&x[c3 * (DF / 2) + lane]);
            __half2 v4 = __ldg(&x[c4 * (DF / 2) + lane]);
            __half2 v5 = __ldg(&x[c5 * (DF / 2) + lane]);
            __half2 v6 = __ldg(&x[c6 * (DF / 2) + lane]);
            __half2 v7 = __ldg(&x[c7 * (DF / 2) + lane]);
            float2 f0 = __half22float2(v0); a0 += f0.x; a1 += f0.y;
            float2 f1 = __half22float2(v1); a0 += f1.x; a1 += f1.y;
            float2 f2 = __half22float2(v2); a0 += f2.x; a1 += f2.y;
            float2 f3 = __half22float2(v3); a0 += f3.x; a1 += f3.y;
            float2 f4 = __half22float2(v4); a0 += f4.x; a1 += f4.y;
            float2 f5 = __half22float2(v5); a0 += f5.x; a1 += f5.y;
            float2 f6 = __half22float2(v6); a0 += f6.x; a1 += f6.y;
            float2 f7 = __half22float2(v7); a0 += f7.x; a1 += f7.y;
        }
        for (; j < n; j++) {
            int cj = __shfl_sync(0xffffffffu, c, j);
            float2 f = __half22float2(__ldg(&x[cj * (DF / 2) + lane]));
            a0 += f.x;
            a1 += f.y;
        }
    }
    return make_float2(a0, a1);
}

// hop-1: t1h[i] = dd[i] * sum_{masked e} uh[col_e]  (masked CSR)
__global__ void __launch_bounds__(256)
hop1_kernel() {
    int wi = (blockIdx.x * blockDim.x + threadIdx.x) >> 5;
    if (wi >= NN) return;
    int lane = threadIdx.x & 31;
    float2 sum = row_gather(g_uh, g_ecol1, g_rp1[wi], g_rp1[wi + 1], lane);
    float sc = g_dd[wi];
    g_t1h[wi * (DF / 2) + lane] = __floats2half2_rn(sc * sum.x, sc * sum.y);
}

// hop-2 + RK4 epilogue. v = -dinv_r[i] * sum_e t1h[col_e]  (full CSR)
// MODE 1 (k1): acc  = v;  u = rh + 0.5*dt*v        (rh = fp16 copy of r)
// MODE 2 (k2): acc += 2v; u = rh + 0.5*dt*v
// MODE 3 (k3): acc += 2v; u = rh +     dt*v
// MODE 4 (k4): rnext = r + dt/6*(acc + v) [fp32];  u = rnext; rh = rnext
template <int MODE>
__global__ void __launch_bounds__(256)
hop2_kernel(const float* __restrict__ rin, float* __restrict__ outparam) {
    int wi = (blockIdx.x * blockDim.x + threadIdx.x) >> 5;
    if (wi >= NN) return;
    int lane = threadIdx.x & 31;
    float2 sum = row_gather(g_t1h, g_ecol2, g_rp2[wi], g_rp2[wi + 1], lane);
    float sr = g_dinv_r[wi];
    float v0 = -sr * sum.x;
    float v1 = -sr * sum.y;

    int o = wi * (DF / 2) + lane;
    float p = g_premul[wi];

    if (MODE == 1) {
        g_acc[o] = make_float2(v0, v1);
        float2 rh = __half22float2(g_rh[o]);
        float u0 = rh.x + HALF_DT * v0, u1 = rh.y + HALF_DT * v1;
        g_uh[o] = __floats2half2_rn(p * u0, p * u1);
    } else if (MODE == 2) {
        float2 a = g_acc[o];
        g_acc[o] = make_float2(a.x + 2.0f * v0, a.y + 2.0f * v1);
        float2 rh = __half22float2(g_rh[o]);
        float u0 = rh.x + HALF_DT * v0, u1 = rh.y + HALF_DT * v1;
        g_uh[o] = __floats2half2_rn(p * u0, p * u1);
    } else if (MODE == 3) {
        float2 a = g_acc[o];
        g_acc[o] = make_float2(a.x + 2.0f * v0, a.y + 2.0f * v1);
        float2 rh = __half22float2(g_rh[o]);
        float u0 = rh.x + DTC * v0, u1 = rh.y + DTC * v1;
        g_uh[o] = __floats2half2_rn(p * u0, p * u1);
    } else {  // MODE 4
        float2 a = g_acc[o];
        float2 r2 = ((const float2*)rin)[o];
        float rn0 = r2.x + DT6 * (a.x + v0);
        float rn1 = r2.y + DT6 * (a.y + v1);
        ((float2*)outparam)[o] = make_float2(rn0, rn1);
        g_rh[o] = __floats2half2_rn(rn0, rn1);
        g_uh[o] = __floats2half2_rn(p * rn0, p * rn1);  // next step's k1 input
    }
}

// ---------------- launch ----------------
extern "C" void kernel_launch(void* const* d_in, const int* in_sizes, int n_in,
                              void* d_out, int out_size) {
    const float* r0   = (const float*)d_in[0];
    const int*   eidx = (const int*)d_in[1];
    const int*   mask = (const int*)d_in[2];
    const int* row = eidx;
    const int* col = eidx + NE;
    float* out = (float*)d_out;

    // CSR + normalization build (no device-global symbols passed from host!)
    zero_kernel<<<(NN + 255) / 256, 256>>>();
    hist_kernel<<<(NE + 255) / 256, 256>>>(row, col, mask);
    dinv_kernel<<<(NN + 255) / 256, 256>>>(mask);
    scan_block_fused<<<2 * NB, 1024>>>();
    scan_part_fused <<<1, 64>>>();
    scan_add_fused  <<<2 * NB, 1024>>>();
    scatter_kernel  <<<(NE + 255) / 256, 256>>>(row, col, mask);

    // slice 0 = r0; uh = premul * r0; rh = fp16(r0)
    cudaMemcpyAsync(out, r0, (size_t)NN * DF * sizeof(float),
                    cudaMemcpyDeviceToDevice, 0);
    init_u_kernel<<<(NN * DF / 2 + 255) / 256, 256>>>(r0);

    const int blocks = (NN * 32 + 255) / 256;  // warp per row

    for (int step = 0; step < 5; step++) {
        const float* r = out + (size_t)step * NN * DF;
        float* rnext   = out + (size_t)(step + 1) * NN * DF;

        hop1_kernel   <<<blocks, 256>>>();
        hop2_kernel<1><<<blocks, 256>>>(r, nullptr);
        hop1_kernel   <<<blocks, 256>>>();
        hop2_kernel<2><<<blocks, 256>>>(r, nullptr);
        hop1_kernel   <<<blocks, 256>>>();
        hop2_kernel<3><<<blocks, 256>>>(r, nullptr);
        hop1_kernel   <<<blocks, 256>>>();
        hop2_kernel<4><<<blocks, 256>>>(r, rnext);
    }
}

// round 11
// speedup vs baseline: 1.6112x; 1.3090x over previous
#include <cuda_runtime.h>
#include <cuda_fp16.h>
#include <cstdint>

#define NN 100000
#define DF 64
#define NE 1600000
#define NB ((NN + 1023) / 1024)   // 98 scan blocks

static constexpr float DTC     = 0.2f;
static constexpr float HALF_DT = 0.1f;
static constexpr float DT6     = 0.2f / 6.0f;

// ---------------- scratch (static device globals) ----------------
__device__ int     g_deg1[NN];          // masked row degree (hop-1 CSR)
__device__ int     g_deg2[NN];          // full row degree   (hop-2 CSR)
__device__ int     g_deg_c[NN];         // full col degree
__device__ int     g_cur1[NN];
__device__ int     g_cur2[NN];
__device__ float   g_dinv_r[NN];        // row factor (applied to warp sum)
__device__ float   g_premul[NN];        // mask * dinv_c (folded into u)
__device__ float   g_dd[NN];            // dinv_r * dinv_c (folded into t1)
__device__ int     g_rp1[NN + 1];
__device__ int     g_rp2[NN + 1];
__device__ int     g_part1[NB];
__device__ int     g_part2[NB];
__device__ int     g_ecol1[NE];         // masked CSR cols (~half used)
__device__ int     g_ecol2[NE];         // full CSR cols
__device__ __half2 g_uh [NN * DF / 2];  // stage input * mask*dinv_c, fp16
__device__ __half2 g_t1h[NN * DF / 2];  // hop-1 out * dinv_r*dinv_c, fp16
__device__ __half2 g_rh [NN * DF / 2];  // fp16 copy of current state r
__device__ float4  g_acc[NN * DF / 4];  // k1 + 2k2 + 2k3

// ---------------- preprocessing ----------------
__global__ void zero_kernel() {
    int i = blockIdx.x * blockDim.x + threadIdx.x;
    if (i < NN) { g_deg1[i] = 0; g_deg2[i] = 0; g_deg_c[i] = 0;
                  g_cur1[i] = 0; g_cur2[i] = 0; }
}

__global__ void hist_kernel(const int* __restrict__ row, const int* __restrict__ col,
                            const int* __restrict__ mask) {
    int e = blockIdx.x * blockDim.x + threadIdx.x;
    if (e < NE) {
        int r = row[e], c = col[e];
        atomicAdd(&g_deg2[r], 1);
        atomicAdd(&g_deg_c[c], 1);
        if (mask[c]) atomicAdd(&g_deg1[r], 1);
    }
}

__global__ void dinv_kernel(const int* __restrict__ mask) {
    int i = blockIdx.x * blockDim.x + threadIdx.x;
    if (i < NN) {
        int dr = g_deg2[i];
        int dc = g_deg_c[i];
        float ir = dr > 0 ? rsqrtf((float)dr) : 0.0f;
        float ic = dc > 0 ? rsqrtf((float)dc) : 0.0f;
        g_dinv_r[i] = ir;
        g_premul[i] = mask[i] ? ic : 0.0f;
        g_dd[i]     = ir * ic;
    }
}

// Fused two-level scans for BOTH CSRs (blocks [0,NB) -> CSR1, [NB,2NB) -> CSR2)
__global__ void scan_block_fused() {
    int bb = blockIdx.x;
    int isP2 = (bb >= NB);
    int b = isP2 ? bb - NB : bb;
    const int* __restrict__ deg = isP2 ? g_deg2  : g_deg1;
    int* __restrict__ rp        = isP2 ? g_rp2   : g_rp1;
    int* __restrict__ part      = isP2 ? g_part2 : g_part1;
    __shared__ int wsum[32];
    int t = threadIdx.x, lane = t & 31, wid = t >> 5;
    int i = b * 1024 + t;
    int v = (i < NN) ? deg[i] : 0;
    int incl = v;
    #pragma unroll
    for (int off = 1; off < 32; off <<= 1) {
        int x = __shfl_up_sync(0xffffffffu, incl, off);
        if (lane >= off) incl += x;
    }
    if (lane == 31) wsum[wid] = incl;
    __syncthreads();
    if (wid == 0) {
        int ws = wsum[lane];
        int wincl = ws;
        #pragma unroll
        for (int off = 1; off < 32; off <<= 1) {
            int x = __shfl_up_sync(0xffffffffu, wincl, off);
            if (lane >= off) wincl += x;
        }
        wsum[lane] = wincl - ws;
    }
    __syncthreads();
    int excl = incl - v + wsum[wid];
    if (i < NN) rp[i] = excl;
    if (t == 1023) part[b] = excl + v;
}

__global__ void scan_part_fused() {
    int t = threadIdx.x;
    if (t == 0) {
        int s = 0;
        for (int b = 0; b < NB; b++) { int v = g_part1[b]; g_part1[b] = s; s += v; }
        g_rp1[NN] = s;
    } else if (t == 32) {
        int s = 0;
        for (int b = 0; b < NB; b++) { int v = g_part2[b]; g_part2[b] = s; s += v; }
        g_rp2[NN] = s;
    }
}

__global__ void scan_add_fused() {
    int bb = blockIdx.x;
    int isP2 = (bb >= NB);
    int b = isP2 ? bb - NB : bb;
    int* __restrict__ rp         = isP2 ? g_rp2   : g_rp1;
    const int* __restrict__ part = isP2 ? g_part2 : g_part1;
    int i = b * 1024 + threadIdx.x;
    if (i < NN) rp[i] += part[b];
}

__global__ void scatter_kernel(const int* __restrict__ row, const int* __restrict__ col,
                               const int* __restrict__ mask) {
    int e = blockIdx.x * blockDim.x + threadIdx.x;
    if (e < NE) {
        int r = row[e], c = col[e];
        int p2 = g_rp2[r] + atomicAdd(&g_cur2[r], 1);
        g_ecol2[p2] = c;
        if (mask[c]) {
            int p1 = g_rp1[r] + atomicAdd(&g_cur1[r], 1);
            g_ecol1[p1] = c;
        }
    }
}

// uh = mask*dinv_c * r0; rh = fp16(r0)
__global__ void init_u_kernel(const float* __restrict__ r0) {
    int i = blockIdx.x * blockDim.x + threadIdx.x;   // float2 index
    if (i < NN * DF / 2) {
        int node = i >> 5;
        float p = g_premul[node];
        float2 r = ((const float2*)r0)[i];
        g_uh[i] = __floats2half2_rn(p * r.x, p * r.y);
        g_rh[i] = __floats2half2_rn(r.x, r.y);
    }
}

// -------- gather core: HALF-WARP per row (2 rows per warp), uint2 loads --------
// Lanes 0-15 own row 2w, lanes 16-31 own row 2w+1. Lane m loads features
// 4m..4m+3 (uint2, 8B). One LDG.64 warp-instruction gathers one edge for EACH
// half -> per-edge LDG/SHFL cost halves. Warp-uniform loop to nmax keeps the
// halves converged; shorter half's loads are predicated (accumulate zeros).
__device__ __forceinline__ float4
row_gather_half(const __half2* __restrict__ x, const int* __restrict__ ec,
                const int* __restrict__ rp, int row, int m) {
    int s = rp[row];
    int n_my = rp[row + 1] - s;
    int n_other = __shfl_xor_sync(0xffffffffu, n_my, 16);
    int nmax = max(n_my, n_other);
    const char* __restrict__ xb = (const char*)x;
    unsigned moff = m << 3;
    float a0 = 0.f, a1 = 0.f, a2 = 0.f, a3 = 0.f;

    for (int j0 = 0; j0 < nmax; j0 += 16) {
        int myidx = j0 + m;
        int c = (myidx < n_my) ? __ldg(&ec[s + myidx]) : 0;
        #pragma unroll
        for (int g = 0; g < 4; g++) {
            int b = j0 + g * 4;
            if (b >= nmax) break;                 // warp-uniform
            int c0 = __shfl_sync(0xffffffffu, c, g * 4 + 0, 16);
            int c1 = __shfl_sync(0xffffffffu, c, g * 4 + 1, 16);
            int c2 = __shfl_sync(0xffffffffu, c, g * 4 + 2, 16);
            int c3 = __shfl_sync(0xffffffffu, c, g * 4 + 3, 16);
            uint2 z = make_uint2(0u, 0u);
            uint2 v0 = (b + 0 < n_my) ? __ldg((const uint2*)(xb + (((size_t)c0) << 7) + moff)) : z;
            uint2 v1 = (b + 1 < n_my) ? __ldg((const uint2*)(xb + (((size_t)c1) << 7) + moff)) : z;
            uint2 v2 = (b + 2 < n_my) ? __ldg((const uint2*)(xb + (((size_t)c2) << 7) + moff)) : z;
            uint2 v3 = (b + 3 < n_my) ? __ldg((const uint2*)(xb + (((size_t)c3) << 7) + moff)) : z;
            float2 f;
            f = __half22float2(*(const __half2*)&v0.x); a0 += f.x; a1 += f.y;
            f = __half22float2(*(const __half2*)&v0.y); a2 += f.x; a3 += f.y;
            f = __half22float2(*(const __half2*)&v1.x); a0 += f.x; a1 += f.y;
            f = __half22float2(*(const __half2*)&v1.y); a2 += f.x; a3 += f.y;
            f = __half22float2(*(const __half2*)&v2.x); a0 += f.x; a1 += f.y;
            f = __half22float2(*(const __half2*)&v2.y); a2 += f.x; a3 += f.y;
            f = __half22float2(*(const __half2*)&v3.x); a0 += f.x; a1 += f.y;
            f = __half22float2(*(const __half2*)&v3.y); a2 += f.x; a3 += f.y;
        }
    }
    return make_float4(a0, a1, a2, a3);
}

// hop-1: t1h[row] = dd[row] * sum_{masked e} uh[col_e]
__global__ void __launch_bounds__(256)
hop1_kernel() {
    int w = (blockIdx.x * blockDim.x + threadIdx.x) >> 5;
    if (w >= NN / 2) return;
    int lane = threadIdx.x & 31;
    int m = lane & 15;
    int row = w * 2 + (lane >> 4);
    float4 sum = row_gather_half(g_uh, g_ecol1, g_rp1, row, m);
    float sc = g_dd[row];
    __half2 h0 = __floats2half2_rn(sc * sum.x, sc * sum.y);
    __half2 h1 = __floats2half2_rn(sc * sum.z, sc * sum.w);
    ((uint2*)g_t1h)[row * 16 + m] =
        make_uint2(*(const unsigned*)&h0, *(const unsigned*)&h1);
}

// hop-2 + RK4 epilogue. v = -dinv_r[row] * sum_e t1h[col_e]
// MODE 1 (k1): acc  = v;  u = rh + 0.5*dt*v      (rh = fp16 copy of r)
// MODE 2 (k2): acc += 2v; u = rh + 0.5*dt*v
// MODE 3 (k3): acc += 2v; u = rh +     dt*v
// MODE 4 (k4): rnext = r + dt/6*(acc+v) [fp32];  u = rnext; rh = rnext
template <int MODE>
__global__ void __launch_bounds__(256)
hop2_kernel(const float* __restrict__ rin, float* __restrict__ outparam) {
    int w = (blockIdx.x * blockDim.x + threadIdx.x) >> 5;
    if (w >= NN / 2) return;
    int lane = threadIdx.x & 31;
    int m = lane & 15;
    int row = w * 2 + (lane >> 4);
    float4 sum = row_gather_half(g_t1h, g_ecol2, g_rp2, row, m);
    float sr = g_dinv_r[row];
    float v0 = -sr * sum.x, v1 = -sr * sum.y, v2 = -sr * sum.z, v3 = -sr * sum.w;

    int o = row * 16 + m;                        // float4 / uint2 index
    float p = g_premul[row];

    float u0, u1, u2, u3;
    if (MODE == 1) {
        g_acc[o] = make_float4(v0, v1, v2, v3);
        uint2 rh2 = ((const uint2*)g_rh)[o];
        float2 ra = __half22float2(*(const __half2*)&rh2.x);
        float2 rb = __half22float2(*(const __half2*)&rh2.y);
        u0 = ra.x + HALF_DT * v0; u1 = ra.y + HALF_DT * v1;
        u2 = rb.x + HALF_DT * v2; u3 = rb.y + HALF_DT * v3;
    } else if (MODE == 2 || MODE == 3) {
        float4 a = g_acc[o];
        g_acc[o] = make_float4(a.x + 2.f * v0, a.y + 2.f * v1,
                               a.z + 2.f * v2, a.w + 2.f * v3);
        uint2 rh2 = ((const uint2*)g_rh)[o];
        float2 ra = __half22float2(*(const __half2*)&rh2.x);
        float2 rb = __half22float2(*(const __half2*)&rh2.y);
        float cdt = (MODE == 2) ? HALF_DT : DTC;
        u0 = ra.x + cdt * v0; u1 = ra.y + cdt * v1;
        u2 = rb.x + cdt * v2; u3 = rb.y + cdt * v3;
    } else {  // MODE 4
        float4 a = g_acc[o];
        float4 r4 = ((const float4*)rin)[o];
        u0 = r4.x + DT6 * (a.x + v0); u1 = r4.y + DT6 * (a.y + v1);
        u2 = r4.z + DT6 * (a.z + v2); u3 = r4.w + DT6 * (a.w + v3);
        ((float4*)outparam)[o] = make_float4(u0, u1, u2, u3);
        __half2 rh0 = __floats2half2_rn(u0, u1);
        __half2 rh1 = __floats2half2_rn(u2, u3);
        ((uint2*)g_rh)[o] = make_uint2(*(const unsigned*)&rh0, *(const unsigned*)&rh1);
    }
    __half2 h0 = __floats2half2_rn(p * u0, p * u1);
    __half2 h1 = __floats2half2_rn(p * u2, p * u3);
    ((uint2*)g_uh)[o] = make_uint2(*(const unsigned*)&h0, *(const unsigned*)&h1);
}

// ---------------- launch ----------------
extern "C" void kernel_launch(void* const* d_in, const int* in_sizes, int n_in,
                              void* d_out, int out_size) {
    const float* r0   = (const float*)d_in[0];
    const int*   eidx = (const int*)d_in[1];
    const int*   mask = (const int*)d_in[2];
    const int* row = eidx;
    const int* col = eidx + NE;
    float* out = (float*)d_out;

    // CSR + normalization build (no device-global symbols passed from host!)
    zero_kernel<<<(NN + 255) / 256, 256>>>();
    hist_kernel<<<(NE + 255) / 256, 256>>>(row, col, mask);
    dinv_kernel<<<(NN + 255) / 256, 256>>>(mask);
    scan_block_fused<<<2 * NB, 1024>>>();
    scan_part_fused <<<1, 64>>>();
    scan_add_fused  <<<2 * NB, 1024>>>();
    scatter_kernel  <<<(NE + 255) / 256, 256>>>(row, col, mask);

    // slice 0 = r0; uh = premul * r0; rh = fp16(r0)
    cudaMemcpyAsync(out, r0, (size_t)NN * DF * sizeof(float),
                    cudaMemcpyDeviceToDevice, 0);
    init_u_kernel<<<(NN * DF / 2 + 255) / 256, 256>>>(r0);

    const int blocks = (NN / 2 * 32 + 255) / 256;  // half-warp per row

    for (int step = 0; step < 5; step++) {
        const float* r = out + (size_t)step * NN * DF;
        float* rnext   = out + (size_t)(step + 1) * NN * DF;

        hop1_kernel   <<<blocks, 256>>>();
        hop2_kernel<1><<<blocks, 256>>>(r, nullptr);
        hop1_kernel   <<<blocks, 256>>>();
        hop2_kernel<2><<<blocks, 256>>>(r, nullptr);
        hop1_kernel   <<<blocks, 256>>>();
        hop2_kernel<3><<<blocks, 256>>>(r, nullptr);
        hop1_kernel   <<<blocks, 256>>>();
        hop2_kernel<4><<<blocks, 256>>>(r, rnext);
    }
}

// round 12
// speedup vs baseline: 1.7550x; 1.0893x over previous
#include <cuda_runtime.h>
#include <cuda_fp16.h>
#include <cstdint>

#define NN 100000
#define DF 64
#define NE 1600000
#define NB ((NN + 1023) / 1024)   // 98 scan blocks

static constexpr float DTC     = 0.2f;
static constexpr float HALF_DT = 0.1f;
static constexpr float DT6     = 0.2f / 6.0f;

// ---------------- scratch (static device globals) ----------------
__device__ int     g_deg1[NN];          // masked row degree (hop-1 CSR)
__device__ int     g_deg2[NN];          // full row degree   (hop-2 CSR)
__device__ int     g_deg_c[NN];         // full col degree
__device__ int     g_cur1[NN];
__device__ int     g_cur2[NN];
__device__ float   g_dinv_r[NN];        // row factor (applied to row sum)
__device__ float   g_premul[NN];        // mask * dinv_c (folded into u)
__device__ float   g_dd[NN];            // dinv_r * dinv_c (folded into t1)
__device__ int     g_rp1[NN + 1];
__device__ int     g_rp2[NN + 1];
__device__ int     g_part1[NB];
__device__ int     g_part2[NB];
__device__ int     g_ecol1[NE];         // masked CSR cols (~half used)
__device__ int     g_ecol2[NE];         // full CSR cols
__device__ __half2 g_uh [NN * DF / 2];  // stage input * mask*dinv_c, fp16
__device__ __half2 g_t1h[NN * DF / 2];  // hop-1 out * dinv_r*dinv_c, fp16
__device__ __half2 g_rh [NN * DF / 2];  // fp16 copy of current state r
__device__ float4  g_acc[NN * DF / 4];  // k1 + 2k2 + 2k3

// ---------------- preprocessing ----------------
__global__ void zero_kernel() {
    int i = blockIdx.x * blockDim.x + threadIdx.x;
    if (i < NN) { g_deg1[i] = 0; g_deg2[i] = 0; g_deg_c[i] = 0;
                  g_cur1[i] = 0; g_cur2[i] = 0; }
}

__global__ void hist_kernel(const int* __restrict__ row, const int* __restrict__ col,
                            const int* __restrict__ mask) {
    int e = blockIdx.x * blockDim.x + threadIdx.x;
    if (e < NE) {
        int r = row[e], c = col[e];
        atomicAdd(&g_deg2[r], 1);
        atomicAdd(&g_deg_c[c], 1);
        if (mask[c]) atomicAdd(&g_deg1[r], 1);
    }
}

__global__ void dinv_kernel(const int* __restrict__ mask) {
    int i = blockIdx.x * blockDim.x + threadIdx.x;
    if (i < NN) {
        int dr = g_deg2[i];
        int dc = g_deg_c[i];
        float ir = dr > 0 ? rsqrtf((float)dr) : 0.0f;
        float ic = dc > 0 ? rsqrtf((float)dc) : 0.0f;
        g_dinv_r[i] = ir;
        g_premul[i] = mask[i] ? ic : 0.0f;
        g_dd[i]     = ir * ic;
    }
}

// Fused two-level scans for BOTH CSRs (blocks [0,NB) -> CSR1, [NB,2NB) -> CSR2)
__global__ void scan_block_fused() {
    int bb = blockIdx.x;
    int isP2 = (bb >= NB);
    int b = isP2 ? bb - NB : bb;
    const int* __restrict__ deg = isP2 ? g_deg2  : g_deg1;
    int* __restrict__ rp        = isP2 ? g_rp2   : g_rp1;
    int* __restrict__ part      = isP2 ? g_part2 : g_part1;
    __shared__ int wsum[32];
    int t = threadIdx.x, lane = t & 31, wid = t >> 5;
    int i = b * 1024 + t;
    int v = (i < NN) ? deg[i] : 0;
    int incl = v;
    #pragma unroll
    for (int off = 1; off < 32; off <<= 1) {
        int x = __shfl_up_sync(0xffffffffu, incl, off);
        if (lane >= off) incl += x;
    }
    if (lane == 31) wsum[wid] = incl;
    __syncthreads();
    if (wid == 0) {
        int ws = wsum[lane];
        int wincl = ws;
        #pragma unroll
        for (int off = 1; off < 32; off <<= 1) {
            int x = __shfl_up_sync(0xffffffffu, wincl, off);
            if (lane >= off) wincl += x;
        }
        wsum[lane] = wincl - ws;
    }
    __syncthreads();
    int excl = incl - v + wsum[wid];
    if (i < NN) rp[i] = excl;
    if (t == 1023) part[b] = excl + v;
}

__global__ void scan_part_fused() {
    int t = threadIdx.x;
    if (t == 0) {
        int s = 0;
        for (int b = 0; b < NB; b++) { int v = g_part1[b]; g_part1[b] = s; s += v; }
        g_rp1[NN] = s;
    } else if (t == 32) {
        int s = 0;
        for (int b = 0; b < NB; b++) { int v = g_part2[b]; g_part2[b] = s; s += v; }
        g_rp2[NN] = s;
    }
}

__global__ void scan_add_fused() {
    int bb = blockIdx.x;
    int isP2 = (bb >= NB);
    int b = isP2 ? bb - NB : bb;
    int* __restrict__ rp         = isP2 ? g_rp2   : g_rp1;
    const int* __restrict__ part = isP2 ? g_part2 : g_part1;
    int i = b * 1024 + threadIdx.x;
    if (i < NN) rp[i] += part[b];
}

__global__ void scatter_kernel(const int* __restrict__ row, const int* __restrict__ col,
                               const int* __restrict__ mask) {
    int e = blockIdx.x * blockDim.x + threadIdx.x;
    if (e < NE) {
        int r = row[e], c = col[e];
        int p2 = g_rp2[r] + atomicAdd(&g_cur2[r], 1);
        g_ecol2[p2] = c;
        if (mask[c]) {
            int p1 = g_rp1[r] + atomicAdd(&g_cur1[r], 1);
            g_ecol1[p1] = c;
        }
    }
}

// uh = mask*dinv_c * r0; rh = fp16(r0)
__global__ void init_u_kernel(const float* __restrict__ r0) {
    int i = blockIdx.x * blockDim.x + threadIdx.x;   // float2 index
    if (i < NN * DF / 2) {
        int node = i >> 5;
        float p = g_premul[node];
        float2 r = ((const float2*)r0)[i];
        g_uh[i] = __floats2half2_rn(p * r.x, p * r.y);
        g_rh[i] = __floats2half2_rn(r.x, r.y);
    }
}

// ------ gather core: QUARTER-WARP per row (4 rows/warp), uint4 (16B) loads ------
// Lane m (0..7) of quarter q owns features 8m..8m+7 of row 4w+q. One LDG.128
// warp-instruction gathers one edge for each of the 4 rows. Warp-uniform loop
// to nmax (max degree of the quad); shorter rows' loads predicated to zero.
struct Acc8 { float a0, a1, a2, a3, a4, a5, a6, a7; };

#define QACC(v) \
    { float2 f; \
      f = __half22float2(*(const __half2*)&(v).x); r.a0 += f.x; r.a1 += f.y; \
      f = __half22float2(*(const __half2*)&(v).y); r.a2 += f.x; r.a3 += f.y; \
      f = __half22float2(*(const __half2*)&(v).z); r.a4 += f.x; r.a5 += f.y; \
      f = __half22float2(*(const __half2*)&(v).w); r.a6 += f.x; r.a7 += f.y; }

__device__ __forceinline__ Acc8
row_gather_quarter(const __half2* __restrict__ x, const int* __restrict__ ec,
                   const int* __restrict__ rp, int row, int m) {
    int s = rp[row];
    int n_my = rp[row + 1] - s;
    int t = __shfl_xor_sync(0xffffffffu, n_my, 8);
    int nmax = max(n_my, t);
    t = __shfl_xor_sync(0xffffffffu, nmax, 16);
    nmax = max(nmax, t);
    const char* __restrict__ xb = (const char*)x;
    unsigned moff = m << 4;                       // 16 B per lane
    Acc8 r = {0.f, 0.f, 0.f, 0.f, 0.f, 0.f, 0.f, 0.f};

    for (int j0 = 0; j0 < nmax; j0 += 8) {
        int myidx = j0 + m;
        int c = (myidx < n_my) ? __ldg(&ec[s + myidx]) : 0;
        #pragma unroll
        for (int g = 0; g < 2; g++) {
            int b = j0 + g * 4;
            if (b >= nmax) break;                 // warp-uniform
            int c0 = __shfl_sync(0xffffffffu, c, g * 4 + 0, 8);
            int c1 = __shfl_sync(0xffffffffu, c, g * 4 + 1, 8);
            int c2 = __shfl_sync(0xffffffffu, c, g * 4 + 2, 8);
            int c3 = __shfl_sync(0xffffffffu, c, g * 4 + 3, 8);
            uint4 z = make_uint4(0u, 0u, 0u, 0u);
            uint4 v0 = (b + 0 < n_my) ? __ldg((const uint4*)(xb + (((size_t)c0) << 7) + moff)) : z;
            uint4 v1 = (b + 1 < n_my) ? __ldg((const uint4*)(xb + (((size_t)c1) << 7) + moff)) : z;
            uint4 v2 = (b + 2 < n_my) ? __ldg((const uint4*)(xb + (((size_t)c2) << 7) + moff)) : z;
            uint4 v3 = (b + 3 < n_my) ? __ldg((const uint4*)(xb + (((size_t)c3) << 7) + moff)) : z;
            QACC(v0) QACC(v1) QACC(v2) QACC(v3)
        }
    }
    return r;
}

// hop-1: t1h[row] = dd[row] * sum_{masked e} uh[col_e]
__global__ void __launch_bounds__(256)
hop1_kernel() {
    int w = (blockIdx.x * blockDim.x + threadIdx.x) >> 5;
    if (w >= NN / 4) return;
    int lane = threadIdx.x & 31;
    int m = lane & 7;
    int row = w * 4 + (lane >> 3);
    Acc8 r = row_gather_quarter(g_uh, g_ecol1, g_rp1, row, m);
    float sc = g_dd[row];
    __half2 h0 = __floats2half2_rn(sc * r.a0, sc * r.a1);
    __half2 h1 = __floats2half2_rn(sc * r.a2, sc * r.a3);
    __half2 h2 = __floats2half2_rn(sc * r.a4, sc * r.a5);
    __half2 h3 = __floats2half2_rn(sc * r.a6, sc * r.a7);
    ((uint4*)g_t1h)[row * 8 + m] =
        make_uint4(*(const unsigned*)&h0, *(const unsigned*)&h1,
                   *(const unsigned*)&h2, *(const unsigned*)&h3);
}

// hop-2 + RK4 epilogue. v = -dinv_r[row] * sum_e t1h[col_e]
// MODE 1 (k1): acc  = v;  u = rh + 0.5*dt*v      (rh = fp16 copy of r)
// MODE 2 (k2): acc += 2v; u = rh + 0.5*dt*v
// MODE 3 (k3): acc += 2v; u = rh +     dt*v
// MODE 4 (k4): rnext = r + dt/6*(acc+v) [fp32];  u = rnext; rh = rnext
template <int MODE>
__global__ void __launch_bounds__(256)
hop2_kernel(const float* __restrict__ rin, float* __restrict__ outparam) {
    int w = (blockIdx.x * blockDim.x + threadIdx.x) >> 5;
    if (w >= NN / 4) return;
    int lane = threadIdx.x & 31;
    int m = lane & 7;
    int row = w * 4 + (lane >> 3);
    Acc8 g = row_gather_quarter(g_t1h, g_ecol2, g_rp2, row, m);
    float sr = g_dinv_r[row];
    float v0 = -sr * g.a0, v1 = -sr * g.a1, v2 = -sr * g.a2, v3 = -sr * g.a3;
    float v4 = -sr * g.a4, v5 = -sr * g.a5, v6 = -sr * g.a6, v7 = -sr * g.a7;

    int o4 = row * 8 + m;                         // uint4 index (uh/rh)
    int oA = row * 16 + 2 * m;                    // float4 index (acc/rin)
    float p = g_premul[row];

    float u0, u1, u2, u3, u4, u5, u6, u7;
    if (MODE == 1) {
        g_acc[oA]     = make_float4(v0, v1, v2, v3);
        g_acc[oA + 1] = make_float4(v4, v5, v6, v7);
        uint4 rh4 = ((const uint4*)g_rh)[o4];
        float2 fa = __half22float2(*(const __half2*)&rh4.x);
        float2 fb = __half22float2(*(const __half2*)&rh4.y);
        float2 fc = __half22float2(*(const __half2*)&rh4.z);
        float2 fd = __half22float2(*(const __half2*)&rh4.w);
        u0 = fa.x + HALF_DT * v0; u1 = fa.y + HALF_DT * v1;
        u2 = fb.x + HALF_DT * v2; u3 = fb.y + HALF_DT * v3;
        u4 = fc.x + HALF_DT * v4; u5 = fc.y + HALF_DT * v5;
        u6 = fd.x + HALF_DT * v6; u7 = fd.y + HALF_DT * v7;
    } else if (MODE == 2 || MODE == 3) {
        float4 a0 = g_acc[oA];
        float4 a1 = g_acc[oA + 1];
        g_acc[oA]     = make_float4(a0.x + 2.f * v0, a0.y + 2.f * v1,
                                    a0.z + 2.f * v2, a0.w + 2.f * v3);
        g_acc[oA + 1] = make_float4(a1.x + 2.f * v4, a1.y + 2.f * v5,
                                    a1.z + 2.f * v6, a1.w + 2.f * v7);
        uint4 rh4 = ((const uint4*)g_rh)[o4];
        float2 fa = __half22float2(*(const __half2*)&rh4.x);
        float2 fb = __half22float2(*(const __half2*)&rh4.y);
        float2 fc = __half22float2(*(const __half2*)&rh4.z);
        float2 fd = __half22float2(*(const __half2*)&rh4.w);
        float cdt = (MODE == 2) ? HALF_DT : DTC;
        u0 = fa.x + cdt * v0; u1 = fa.y + cdt * v1;
        u2 = fb.x + cdt * v2; u3 = fb.y + cdt * v3;
        u4 = fc.x + cdt * v4; u5 = fc.y + cdt * v5;
        u6 = fd.x + cdt * v6; u7 = fd.y + cdt * v7;
    } else {  // MODE 4
        float4 a0 = g_acc[oA];
        float4 a1 = g_acc[oA + 1];
        float4 ra = ((const float4*)rin)[oA];
        float4 rb = ((const float4*)rin)[oA + 1];
        u0 = ra.x + DT6 * (a0.x + v0); u1 = ra.y + DT6 * (a0.y + v1);
        u2 = ra.z + DT6 * (a0.z + v2); u3 = ra.w + DT6 * (a0.w + v3);
        u4 = rb.x + DT6 * (a1.x + v4); u5 = rb.y + DT6 * (a1.y + v5);
        u6 = rb.z + DT6 * (a1.z + v6); u7 = rb.w + DT6 * (a1.w + v7);
        ((float4*)outparam)[oA]     = make_float4(u0, u1, u2, u3);
        ((float4*)outparam)[oA + 1] = make_float4(u4, u5, u6, u7);
        __half2 rh0 = __floats2half2_rn(u0, u1);
        __half2 rh1 = __floats2half2_rn(u2, u3);
        __half2 rh2 = __floats2half2_rn(u4, u5);
        __half2 rh3 = __floats2half2_rn(u6, u7);
        ((uint4*)g_rh)[o4] = make_uint4(*(const unsigned*)&rh0, *(const unsigned*)&rh1,
                                        *(const unsigned*)&rh2, *(const unsigned*)&rh3);
    }
    __half2 h0 = __floats2half2_rn(p * u0, p * u1);
    __half2 h1 = __floats2half2_rn(p * u2, p * u3);
    __half2 h2 = __floats2half2_rn(p * u4, p * u5);
    __half2 h3 = __floats2half2_rn(p * u6, p * u7);
    ((uint4*)g_uh)[o4] = make_uint4(*(const unsigned*)&h0, *(const unsigned*)&h1,
                                    *(const unsigned*)&h2, *(const unsigned*)&h3);
}

// ---------------- launch ----------------
extern "C" void kernel_launch(void* const* d_in, const int* in_sizes, int n_in,
                              void* d_out, int out_size) {
    const float* r0   = (const float*)d_in[0];
    const int*   eidx = (const int*)d_in[1];
    const int*   mask = (const int*)d_in[2];
    const int* row = eidx;
    const int* col = eidx + NE;
    float* out = (float*)d_out;

    // CSR + normalization build (no device-global symbols passed from host!)
    zero_kernel<<<(NN + 255) / 256, 256>>>();
    hist_kernel<<<(NE + 255) / 256, 256>>>(row, col, mask);
    dinv_kernel<<<(NN + 255) / 256, 256>>>(mask);
    scan_block_fused<<<2 * NB, 1024>>>();
    scan_part_fused <<<1, 64>>>();
    scan_add_fused  <<<2 * NB, 1024>>>();
    scatter_kernel  <<<(NE + 255) / 256, 256>>>(row, col, mask);

    // slice 0 = r0; uh = premul * r0; rh = fp16(r0)
    cudaMemcpyAsync(out, r0, (size_t)NN * DF * sizeof(float),
                    cudaMemcpyDeviceToDevice, 0);
    init_u_kernel<<<(NN * DF / 2 + 255) / 256, 256>>>(r0);

    const int blocks = (NN / 4 * 32 + 255) / 256;  // quarter-warp per row

    for (int step = 0; step < 5; step++) {
        const float* r = out + (size_t)step * NN * DF;
        float* rnext   = out + (size_t)(step + 1) * NN * DF;

        hop1_kernel   <<<blocks, 256>>>();
        hop2_kernel<1><<<blocks, 256>>>(r, nullptr);
        hop1_kernel   <<<blocks, 256>>>();
        hop2_kernel<2><<<blocks, 256>>>(r, nullptr);
        hop1_kernel   <<<blocks, 256>>>();
        hop2_kernel<3><<<blocks, 256>>>(r, nullptr);
        hop1_kernel   <<<blocks, 256>>>();
        hop2_kernel<4><<<blocks, 256>>>(r, rnext);
    }
}